// round 2
// baseline (speedup 1.0000x reference)
#include <cuda_runtime.h>
#include <cstddef>

#define NN 20000
#define EE 320000
#define HH 128
#define KK 4
#define BB 64
#define CAP 64

#define OFF_LOGITS 0
#define OFF_HSTAB  512
#define OFF_HORIG  33280
#define OFF_NM     41472
#define OFF_EM     121472

#define NH4 ((size_t)NN * HH * 4)
#define SMEM_BYTES ((64 * 132 + 128 * 132) * 4)

__device__ __align__(128) unsigned char g_scratch[76913280];

// ---------------- helpers ----------------
__device__ __forceinline__ void ffma2(unsigned long long& d, unsigned long long a, unsigned long long b) {
    asm("fma.rn.f32x2 %0, %1, %2, %0;" : "+l"(d) : "l"(a), "l"(b));
}
__device__ __forceinline__ unsigned long long dup2(float x) {
    unsigned long long r;
    asm("mov.b64 %0, {%1, %1};" : "=l"(r) : "f"(x));
    return r;
}
__device__ __forceinline__ void unpack2(unsigned long long v, float& lo, float& hi) {
    asm("mov.b64 {%0, %1}, %2;" : "=f"(lo), "=f"(hi) : "l"(v));
}

// ---------------- setup ----------------
__global__ void k_zero_counts(int* deg, int* cnt) {
    int i = blockIdx.x * blockDim.x + threadIdx.x;
    if (i < NN) deg[i] = 0;
    if (i < BB) cnt[i] = 0;
}

__global__ void k_zero_nm(float* nm) {
    int i = blockIdx.x * blockDim.x + threadIdx.x;
    if (i < NN * KK) nm[i] = 0.f;
}

__global__ void k_build_adj(const int* __restrict__ src, const int* __restrict__ dst,
                            int* deg, int* adj_src, int* adj_eid) {
    int e = blockIdx.x * blockDim.x + threadIdx.x;
    if (e >= EE) return;
    int d = dst[e];
    int slot = atomicAdd(&deg[d], 1);
    if (slot < CAP) {
        adj_src[d * CAP + slot] = src[e];
        adj_eid[d * CAP + slot] = e;
    }
}

__global__ void k_sort_adj(const int* __restrict__ deg, int* adj_src, int* adj_eid) {
    int n = blockIdx.x * blockDim.x + threadIdx.x;
    if (n >= NN) return;
    int d = deg[n]; if (d > CAP) d = CAP;
    int* es = adj_eid + n * CAP;
    int* ss = adj_src + n * CAP;
    for (int i = 1; i < d; i++) {
        int ke = es[i], ks = ss[i];
        int j = i - 1;
        while (j >= 0 && es[j] > ke) { es[j + 1] = es[j]; ss[j + 1] = ss[j]; j--; }
        es[j + 1] = ke; ss[j + 1] = ks;
    }
}

__global__ void k_count_batch(const int* __restrict__ batch, int* cnt) {
    int n = blockIdx.x * blockDim.x + threadIdx.x;
    if (n < NN) atomicAdd(&cnt[batch[n]], 1);
}

__global__ void k_bstart(const int* __restrict__ cnt, int* bstart) {
    int g = threadIdx.x;
    if (g >= BB) return;
    int s = 0;
    for (int j = 0; j < g; j++) s += cnt[j];
    bstart[g] = s;
}

// ---------------- aggregation (gather, deterministic) ----------------
template <bool WEIGHTED>
__global__ void k_aggregate(const float* __restrict__ h, float* __restrict__ agg,
                            const int* __restrict__ deg, const int* __restrict__ adj_src,
                            const int* __restrict__ adj_eid, const float* __restrict__ eon) {
    int node = blockIdx.x * (blockDim.x >> 5) + (threadIdx.x >> 5);
    if (node >= NN) return;
    int lane = threadIdx.x & 31;
    int d = deg[node]; if (d > CAP) d = CAP;
    const int* ss = adj_src + node * CAP;
    const int* es = adj_eid + node * CAP;
    float4 acc = make_float4(0.f, 0.f, 0.f, 0.f);
    for (int i = 0; i < d; i++) {
        int s = ss[i];
        if (WEIGHTED) {
            float w = eon[es[i]];
            if (w == 0.f) continue;
            float4 v = *(const float4*)(h + (size_t)s * HH + (lane << 2));
            acc.x += w * v.x; acc.y += w * v.y; acc.z += w * v.z; acc.w += w * v.w;
        } else {
            float4 v = *(const float4*)(h + (size_t)s * HH + (lane << 2));
            acc.x += v.x; acc.y += v.y; acc.z += v.z; acc.w += v.w;
        }
    }
    *(float4*)(agg + (size_t)node * HH + (lane << 2)) = acc;
}

// ---------------- GEMM: out = act( ((1+eps)*X + AGG) @ W + b ) ----------------
template <bool HAS_AGG, bool RELU>
__global__ void __launch_bounds__(256, 2)
k_gemm128(const float* __restrict__ X, const float* __restrict__ AGG,
          const float* __restrict__ epsp, const float* __restrict__ W,
          const float* __restrict__ bias, float* __restrict__ out, int M) {
    extern __shared__ float sm[];
    float* As = sm;                // [64][132]
    float* Ws = sm + 64 * 132;     // [128][132]

    int tid = threadIdx.x;
    int row0 = blockIdx.x * 64;
    float ep = 1.f;
    if (HAS_AGG) ep = 1.f + *epsp;

    for (int i = tid; i < 64 * 32; i += 256) {
        int r = i >> 5;
        int c4 = (i & 31) << 2;
        int gr = row0 + r;
        float4 v = make_float4(0.f, 0.f, 0.f, 0.f);
        if (gr < M) {
            v = *(const float4*)(X + (size_t)gr * HH + c4);
            if (HAS_AGG) {
                float4 a = *(const float4*)(AGG + (size_t)gr * HH + c4);
                v.x = ep * v.x + a.x; v.y = ep * v.y + a.y;
                v.z = ep * v.z + a.z; v.w = ep * v.w + a.w;
            }
        }
        *(float4*)&As[r * 132 + c4] = v;
    }
    for (int i = tid; i < 128 * 32; i += 256) {
        int r = i >> 5;
        int c4 = (i & 31) << 2;
        *(float4*)&Ws[r * 132 + c4] = *(const float4*)(W + r * HH + c4);
    }
    __syncthreads();

    int r0 = (tid >> 5) * 8;
    int c0 = (tid & 31) * 4;
    unsigned long long acc[8][2];
#pragma unroll
    for (int i = 0; i < 8; i++) { acc[i][0] = 0ull; acc[i][1] = 0ull; }

    const float* arow = As + r0 * 132;
#pragma unroll 2
    for (int k = 0; k < 128; k += 4) {
        ulonglong2 b0 = *(const ulonglong2*)(Ws + (k + 0) * 132 + c0);
        ulonglong2 b1 = *(const ulonglong2*)(Ws + (k + 1) * 132 + c0);
        ulonglong2 b2 = *(const ulonglong2*)(Ws + (k + 2) * 132 + c0);
        ulonglong2 b3 = *(const ulonglong2*)(Ws + (k + 3) * 132 + c0);
#pragma unroll
        for (int i = 0; i < 8; i++) {
            float4 a4 = *(const float4*)(arow + i * 132 + k);
            unsigned long long ax = dup2(a4.x), ay = dup2(a4.y);
            unsigned long long az = dup2(a4.z), aw = dup2(a4.w);
            ffma2(acc[i][0], ax, b0.x); ffma2(acc[i][1], ax, b0.y);
            ffma2(acc[i][0], ay, b1.x); ffma2(acc[i][1], ay, b1.y);
            ffma2(acc[i][0], az, b2.x); ffma2(acc[i][1], az, b2.y);
            ffma2(acc[i][0], aw, b3.x); ffma2(acc[i][1], aw, b3.y);
        }
    }

    float4 bv = make_float4(0.f, 0.f, 0.f, 0.f);
    if (bias) bv = *(const float4*)(bias + c0);
#pragma unroll
    for (int i = 0; i < 8; i++) {
        int gr = row0 + r0 + i;
        if (gr < M) {
            float x0, x1, x2, x3;
            unpack2(acc[i][0], x0, x1);
            unpack2(acc[i][1], x2, x3);
            x0 += bv.x; x1 += bv.y; x2 += bv.z; x3 += bv.w;
            if (RELU) {
                x0 = fmaxf(x0, 0.f); x1 = fmaxf(x1, 0.f);
                x2 = fmaxf(x2, 0.f); x3 = fmaxf(x3, 0.f);
            }
            *(float4*)(out + (size_t)gr * HH + c0) = make_float4(x0, x1, x2, x3);
        }
    }
}

// ---------------- edge mask (warp per edge) ----------------
__global__ void k_edgemask(int kk, const int* __restrict__ src, const int* __restrict__ dst,
                           const float* __restrict__ u, const float* __restrict__ b1,
                           const float* __restrict__ w2, const float* __restrict__ b2p,
                           float* __restrict__ nm, float* __restrict__ em,
                           float* __restrict__ eon,
                           const float* __restrict__ Abuf, const float* __restrict__ Bbuf) {
    int e = blockIdx.x * (blockDim.x >> 5) + (threadIdx.x >> 5);
    if (e >= EE) return;
    int lane = threadIdx.x & 31;
    int s = src[e], d = dst[e];
    float4 a = *(const float4*)(Abuf + (size_t)s * HH + (lane << 2));
    float4 b = *(const float4*)(Bbuf + (size_t)d * HH + (lane << 2));
    float4 bb = *(const float4*)(b1 + (lane << 2));
    float4 wv = *(const float4*)(w2 + (lane << 2));
    float h0 = fmaxf(a.x + b.x + bb.x, 0.f);
    float h1 = fmaxf(a.y + b.y + bb.y, 0.f);
    float h2 = fmaxf(a.z + b.z + bb.z, 0.f);
    float h3 = fmaxf(a.w + b.w + bb.w, 0.f);
    float p = h0 * wv.x + h1 * wv.y + h2 * wv.z + h3 * wv.w;
#pragma unroll
    for (int off = 16; off; off >>= 1) p += __shfl_xor_sync(0xffffffffu, p, off);
    if (lane == 0) {
        float eml = p + b2p[0];
        float uu = u[(size_t)e * KK + kk];
        float g = -logf(-logf(uu + 1e-20f) + 1e-20f);
        float t = (eml + g) / 0.1f;
        float ys = 1.f / (1.f + expf(-t));
        float hard = (ys > 0.5f) ? 1.f : 0.f;
        float eo = (hard + ys) - ys;   // straight-through forward value, same fp32 ops as ref
        eon[e] = eo;
        em[(size_t)e * KK + kk] = eo;
        if (eo > 0.f) {
            nm[(size_t)s * KK + kk] = 1.f;
            nm[(size_t)d * KK + kk] = 1.f;
        }
    }
}

// ---------------- masked x ----------------
__global__ void k_maskx(const float* __restrict__ x, const float* __restrict__ nm, int kk,
                        float* __restrict__ hout) {
    int i = blockIdx.x * blockDim.x + threadIdx.x;
    if (i >= NN * 32) return;
    int n = i >> 5;
    float m = nm[(size_t)n * KK + kk];
    float4 v = *(const float4*)(x + ((size_t)i << 2));
    v.x *= m; v.y *= m; v.z *= m; v.w *= m;
    *(float4*)(hout + ((size_t)i << 2)) = v;
}

// ---------------- mean pool: grid (B, 4), 32 threads ----------------
__global__ void k_pool(const float* __restrict__ h, float* __restrict__ out_base, int out_stride,
                       float* __restrict__ hs, const int* __restrict__ cnt,
                       const int* __restrict__ bstart) {
    int g = blockIdx.x;
    int c = blockIdx.y * 32 + threadIdx.x;
    int n0 = bstart[g], n = cnt[g];
    float a0 = 0.f, a1 = 0.f, a2 = 0.f, a3 = 0.f;
    int i = 0;
    for (; i + 4 <= n; i += 4) {
        a0 += h[(size_t)(n0 + i + 0) * HH + c];
        a1 += h[(size_t)(n0 + i + 1) * HH + c];
        a2 += h[(size_t)(n0 + i + 2) * HH + c];
        a3 += h[(size_t)(n0 + i + 3) * HH + c];
    }
    float acc = (a0 + a1) + (a2 + a3);
    for (; i < n; i++) acc += h[(size_t)(n0 + i) * HH + c];
    float v = acc / fmaxf((float)n, 1.f);
    out_base[(size_t)g * out_stride + c] = v;
    if (hs) hs[(size_t)g * HH + c] = v;
}

// ---------------- head MLP per graph ----------------
__global__ void k_head(const float* __restrict__ hs, const float* __restrict__ W1,
                       const float* __restrict__ b1, const float* __restrict__ W2,
                       const float* __restrict__ b2, float* __restrict__ outp) {
    __shared__ float sh[128], T[128];
    int g = blockIdx.x, t = threadIdx.x;
    sh[t] = hs[(size_t)g * HH + t];
    __syncthreads();
    float acc = b1[t];
#pragma unroll 8
    for (int i = 0; i < 128; i++) acc += sh[i] * W1[i * HH + t];
    T[t] = fmaxf(acc, 0.f);
    __syncthreads();
    if (t < 2) {
        float s = b2[t];
        for (int i = 0; i < 128; i++) s += T[i] * W2[i * 2 + t];
        outp[(size_t)g * (KK * 2) + t] = s;   // outp pre-offset by k*2
    }
}

// ---------------- launcher ----------------
extern "C" void kernel_launch(void* const* d_in, const int* in_sizes, int n_in,
                              void* d_out, int out_size) {
    const float* x       = (const float*)d_in[0];
    const int*   ei      = (const int*)d_in[1];
    const int*   src     = ei;
    const int*   dst     = ei + EE;
    const int*   batch   = (const int*)d_in[2];
    const float* u       = (const float*)d_in[3];
    const float* enc_W1  = (const float*)d_in[4];
    const float* enc_b1  = (const float*)d_in[5];
    const float* enc_W2  = (const float*)d_in[6];
    const float* enc_b2  = (const float*)d_in[7];
    const float* enc_eps = (const float*)d_in[8];
    const float* cls_W1  = (const float*)d_in[9];
    const float* cls_b1  = (const float*)d_in[10];
    const float* cls_W2  = (const float*)d_in[11];
    const float* cls_b2  = (const float*)d_in[12];
    const float* cls_eps = (const float*)d_in[13];
    const float* mask_W1 = (const float*)d_in[14];
    const float* mask_b1 = (const float*)d_in[15];
    const float* mask_W2 = (const float*)d_in[16];
    const float* mask_b2 = (const float*)d_in[17];
    const float* head_W1 = (const float*)d_in[18];
    const float* head_b1 = (const float*)d_in[19];
    const float* head_W2 = (const float*)d_in[20];
    const float* head_b2 = (const float*)d_in[21];
    float* out = (float*)d_out;

    unsigned char* base = nullptr;
    cudaGetSymbolAddress((void**)&base, g_scratch);
    float* p_h   = (float*)(base + 0 * NH4);
    float* p_t   = (float*)(base + 1 * NH4);
    float* p_agg = (float*)(base + 2 * NH4);
    float* p_Z   = (float*)(base + 3 * NH4);
    float* p_A   = (float*)(base + 4 * NH4);
    float* p_Bm  = (float*)(base + 5 * NH4);
    float* p_eon = (float*)(base + 6 * NH4);
    float* p_hs  = (float*)(base + 6 * NH4 + (size_t)KK * EE * 4);
    unsigned char* ib = base + 6 * NH4 + (size_t)KK * EE * 4 + (size_t)BB * HH * 4;
    int* p_deg     = (int*)(ib);
    int* p_adj_src = (int*)(ib + (size_t)NN * 4);
    int* p_adj_eid = (int*)(ib + (size_t)NN * 4 + (size_t)NN * CAP * 4);
    int* p_cnt     = (int*)(ib + (size_t)NN * 4 + 2ull * NN * CAP * 4);
    int* p_bstart  = p_cnt + BB;

    cudaFuncSetAttribute(k_gemm128<true, true>,   cudaFuncAttributeMaxDynamicSharedMemorySize, SMEM_BYTES);
    cudaFuncSetAttribute(k_gemm128<false, true>,  cudaFuncAttributeMaxDynamicSharedMemorySize, SMEM_BYTES);
    cudaFuncSetAttribute(k_gemm128<false, false>, cudaFuncAttributeMaxDynamicSharedMemorySize, SMEM_BYTES);

    const int GB = (NN + 63) / 64;
    const int AB = (NN + 7) / 8;
    const int EB = (EE + 7) / 8;

    // ---- setup ----
    k_zero_counts<<<(NN + 255) / 256, 256>>>(p_deg, p_cnt);
    k_build_adj<<<(EE + 255) / 256, 256>>>(src, dst, p_deg, p_adj_src, p_adj_eid);
    k_sort_adj<<<(NN + 255) / 256, 256>>>(p_deg, p_adj_src, p_adj_eid);
    k_count_batch<<<(NN + 255) / 256, 256>>>(batch, p_cnt);
    k_bstart<<<1, BB>>>(p_cnt, p_bstart);
    k_zero_nm<<<(NN * KK + 255) / 256, 256>>>(out + OFF_NM);

    // ---- encoder GIN stack: input x -> Z ----
    for (int l = 0; l < 3; l++) {
        const float* hin = (l == 0) ? x : p_h;
        k_aggregate<false><<<AB, 256>>>(hin, p_agg, p_deg, p_adj_src, p_adj_eid, nullptr);
        k_gemm128<true, true><<<GB, 256, SMEM_BYTES>>>(
            hin, p_agg, enc_eps + l, enc_W1 + (size_t)l * HH * HH, enc_b1 + l * HH, p_t, NN);
        float* hout = (l == 2) ? p_Z : p_h;
        k_gemm128<false, true><<<GB, 256, SMEM_BYTES>>>(
            p_t, nullptr, nullptr, enc_W2 + (size_t)l * HH * HH, enc_b2 + l * HH, hout, NN);
    }

    // ---- h_orig ----
    k_pool<<<dim3(BB, 4), 32>>>(p_Z, out + OFF_HORIG, HH, nullptr, p_cnt, p_bstart);

    // ---- experts ----
    for (int k = 0; k < KK; k++) {
        const float* W1top = mask_W1 + (size_t)k * 2 * HH * HH;
        const float* W1bot = W1top + (size_t)HH * HH;
        k_gemm128<false, false><<<GB, 256, SMEM_BYTES>>>(p_Z, nullptr, nullptr, W1top, nullptr, p_A, NN);
        k_gemm128<false, false><<<GB, 256, SMEM_BYTES>>>(p_Z, nullptr, nullptr, W1bot, nullptr, p_Bm, NN);
        k_edgemask<<<EB, 256>>>(k, src, dst, u, mask_b1 + k * HH, mask_W2 + k * HH,
                                mask_b2 + k, out + OFF_NM, out + OFF_EM, p_eon, p_A, p_Bm);
        k_maskx<<<(NN * 32 + 255) / 256, 256>>>(x, out + OFF_NM, k, p_h);
        for (int l = 0; l < 3; l++) {
            int wl = k * 3 + l;
            k_aggregate<true><<<AB, 256>>>(p_h, p_agg, p_deg, p_adj_src, p_adj_eid, p_eon);
            k_gemm128<true, true><<<GB, 256, SMEM_BYTES>>>(
                p_h, p_agg, cls_eps + wl, cls_W1 + (size_t)wl * HH * HH, cls_b1 + wl * HH, p_t, NN);
            k_gemm128<false, true><<<GB, 256, SMEM_BYTES>>>(
                p_t, nullptr, nullptr, cls_W2 + (size_t)wl * HH * HH, cls_b2 + wl * HH, p_h, NN);
        }
        k_pool<<<dim3(BB, 4), 32>>>(p_h, out + OFF_HSTAB + k * HH, KK * HH, p_hs, p_cnt, p_bstart);
        k_head<<<BB, 128>>>(p_hs, head_W1 + (size_t)k * HH * HH, head_b1 + k * HH,
                            head_W2 + (size_t)k * HH * 2, head_b2 + k * 2,
                            out + OFF_LOGITS + k * 2);
    }
}

// round 4
// speedup vs baseline: 1.3035x; 1.3035x over previous
#include <cuda_runtime.h>
#include <cstddef>

#define NN 20000
#define EE 320000
#define HH 128
#define KK 4
#define BB 64
#define CAP 64

#define OFF_LOGITS 0
#define OFF_HSTAB  512
#define OFF_HORIG  33280
#define OFF_NM     41472
#define OFF_EM     121472

#define NH4 ((size_t)NN * HH * 4)
#define SMEM_BYTES ((64 * 132 + 128 * 132) * 4)

// scratch layout
#define SC_Z       0
#define SC_DEG     (SC_Z + NH4)
#define SC_ADJSRC  (SC_DEG + (size_t)NN * 4)
#define SC_ADJEID  (SC_ADJSRC + (size_t)NN * CAP * 4)
#define SC_CNT     (SC_ADJEID + (size_t)NN * CAP * 4)
#define SC_BSTART  (SC_CNT + (size_t)BB * 4)
#define SC_EXP     (SC_BSTART + 384)
#define EXP_STRIDE_F (3 * (size_t)NN * HH + (size_t)EE)   // floats per expert arena
#define SC_TOTAL   (SC_EXP + 4 * EXP_STRIDE_F * 4)

__device__ __align__(128) unsigned char g_scratch[SC_TOTAL];

// ---------------- helpers ----------------
__device__ __forceinline__ void ffma2(unsigned long long& d, unsigned long long a, unsigned long long b) {
    asm("fma.rn.f32x2 %0, %1, %2, %0;" : "+l"(d) : "l"(a), "l"(b));
}
__device__ __forceinline__ unsigned long long dup2(float x) {
    unsigned long long r;
    asm("mov.b64 %0, {%1, %1};" : "=l"(r) : "f"(x));
    return r;
}
__device__ __forceinline__ void unpack2(unsigned long long v, float& lo, float& hi) {
    asm("mov.b64 {%0, %1}, %2;" : "=f"(lo), "=f"(hi) : "l"(v));
}
// per-expert arena pointers (device side)
__device__ __forceinline__ float* arena(int k) {
    return (float*)(g_scratch + SC_EXP) + (size_t)k * EXP_STRIDE_F;
}

// ---------------- setup ----------------
__global__ void k_zero_counts(int* deg, int* cnt) {
    int i = blockIdx.x * blockDim.x + threadIdx.x;
    if (i < NN) deg[i] = 0;
    if (i < BB) cnt[i] = 0;
}

__global__ void k_zero_nm(float* nm) {
    int i = blockIdx.x * blockDim.x + threadIdx.x;
    if (i < NN * KK) nm[i] = 0.f;
}

__global__ void k_build_adj(const int* __restrict__ src, const int* __restrict__ dst,
                            int* deg, int* adj_src, int* adj_eid) {
    int e = blockIdx.x * blockDim.x + threadIdx.x;
    if (e >= EE) return;
    int d = dst[e];
    int slot = atomicAdd(&deg[d], 1);
    if (slot < CAP) {
        adj_src[d * CAP + slot] = src[e];
        adj_eid[d * CAP + slot] = e;
    }
}

__global__ void k_sort_adj(const int* __restrict__ deg, int* adj_src, int* adj_eid) {
    int n = blockIdx.x * blockDim.x + threadIdx.x;
    if (n >= NN) return;
    int d = deg[n]; if (d > CAP) d = CAP;
    int* es = adj_eid + n * CAP;
    int* ss = adj_src + n * CAP;
    for (int i = 1; i < d; i++) {
        int ke = es[i], ks = ss[i];
        int j = i - 1;
        while (j >= 0 && es[j] > ke) { es[j + 1] = es[j]; ss[j + 1] = ss[j]; j--; }
        es[j + 1] = ke; ss[j + 1] = ks;
    }
}

__global__ void k_count_batch(const int* __restrict__ batch, int* cnt) {
    int n = blockIdx.x * blockDim.x + threadIdx.x;
    if (n < NN) atomicAdd(&cnt[batch[n]], 1);
}

__global__ void k_bstart(const int* __restrict__ cnt, int* bstart) {
    int g = threadIdx.x;
    if (g >= BB) return;
    int s = 0;
    for (int j = 0; j < g; j++) s += cnt[j];
    bstart[g] = s;
}

// ---------------- aggregation (gather, deterministic) ----------------
// unweighted (encoder): explicit pointers
__global__ void k_aggregate_enc(const float* __restrict__ h, float* __restrict__ agg,
                                const int* __restrict__ deg, const int* __restrict__ adj_src) {
    int node = blockIdx.x * (blockDim.x >> 5) + (threadIdx.x >> 5);
    if (node >= NN) return;
    int lane = threadIdx.x & 31;
    int d = deg[node]; if (d > CAP) d = CAP;
    const int* ss = adj_src + node * CAP;
    float4 acc = make_float4(0.f, 0.f, 0.f, 0.f);
    for (int i = 0; i < d; i++) {
        float4 v = *(const float4*)(h + (size_t)ss[i] * HH + (lane << 2));
        acc.x += v.x; acc.y += v.y; acc.z += v.z; acc.w += v.w;
    }
    *(float4*)(agg + (size_t)node * HH + (lane << 2)) = acc;
}

// weighted, batched over experts via blockIdx.y: h=arena+0, agg=arena+2NH, eon=arena+3NH
__global__ void k_aggregate_cls(const int* __restrict__ deg, const int* __restrict__ adj_src,
                                const int* __restrict__ adj_eid) {
    int node = blockIdx.x * (blockDim.x >> 5) + (threadIdx.x >> 5);
    if (node >= NN) return;
    int k = blockIdx.y;
    float* a = arena(k);
    const float* h = a;
    float* agg = a + 2 * (size_t)NN * HH;
    const float* eon = a + 3 * (size_t)NN * HH;
    int lane = threadIdx.x & 31;
    int d = deg[node]; if (d > CAP) d = CAP;
    const int* ss = adj_src + node * CAP;
    const int* es = adj_eid + node * CAP;
    float4 acc = make_float4(0.f, 0.f, 0.f, 0.f);
    for (int i = 0; i < d; i++) {
        float w = eon[es[i]];
        if (w == 0.f) continue;
        float4 v = *(const float4*)(h + (size_t)ss[i] * HH + (lane << 2));
        acc.x += w * v.x; acc.y += w * v.y; acc.z += w * v.z; acc.w += w * v.w;
    }
    *(float4*)(agg + (size_t)node * HH + (lane << 2)) = acc;
}

// ---------------- GEMM body ----------------
template <bool HAS_AGG, bool RELU>
__device__ __forceinline__ void gemm_body(float* sm,
          const float* __restrict__ X, const float* __restrict__ AGG,
          const float* __restrict__ epsp, const float* __restrict__ W,
          const float* __restrict__ bias, float* __restrict__ out, int M, int row0) {
    float* As = sm;                // [64][132]
    float* Ws = sm + 64 * 132;     // [128][132]

    int tid = threadIdx.x;
    float ep = 1.f;
    if (HAS_AGG) ep = 1.f + *epsp;

    for (int i = tid; i < 64 * 32; i += 256) {
        int r = i >> 5;
        int c4 = (i & 31) << 2;
        int gr = row0 + r;
        float4 v = make_float4(0.f, 0.f, 0.f, 0.f);
        if (gr < M) {
            v = *(const float4*)(X + (size_t)gr * HH + c4);
            if (HAS_AGG) {
                float4 a = *(const float4*)(AGG + (size_t)gr * HH + c4);
                v.x = ep * v.x + a.x; v.y = ep * v.y + a.y;
                v.z = ep * v.z + a.z; v.w = ep * v.w + a.w;
            }
        }
        *(float4*)&As[r * 132 + c4] = v;
    }
    for (int i = tid; i < 128 * 32; i += 256) {
        int r = i >> 5;
        int c4 = (i & 31) << 2;
        *(float4*)&Ws[r * 132 + c4] = *(const float4*)(W + r * HH + c4);
    }
    __syncthreads();

    int r0 = (tid >> 5) * 8;
    int c0 = (tid & 31) * 4;
    unsigned long long acc[8][2];
#pragma unroll
    for (int i = 0; i < 8; i++) { acc[i][0] = 0ull; acc[i][1] = 0ull; }

    const float* arow = As + r0 * 132;
#pragma unroll 2
    for (int k = 0; k < 128; k += 4) {
        ulonglong2 b0 = *(const ulonglong2*)(Ws + (k + 0) * 132 + c0);
        ulonglong2 b1 = *(const ulonglong2*)(Ws + (k + 1) * 132 + c0);
        ulonglong2 b2 = *(const ulonglong2*)(Ws + (k + 2) * 132 + c0);
        ulonglong2 b3 = *(const ulonglong2*)(Ws + (k + 3) * 132 + c0);
#pragma unroll
        for (int i = 0; i < 8; i++) {
            float4 a4 = *(const float4*)(arow + i * 132 + k);
            unsigned long long ax = dup2(a4.x), ay = dup2(a4.y);
            unsigned long long az = dup2(a4.z), aw = dup2(a4.w);
            ffma2(acc[i][0], ax, b0.x); ffma2(acc[i][1], ax, b0.y);
            ffma2(acc[i][0], ay, b1.x); ffma2(acc[i][1], ay, b1.y);
            ffma2(acc[i][0], az, b2.x); ffma2(acc[i][1], az, b2.y);
            ffma2(acc[i][0], aw, b3.x); ffma2(acc[i][1], aw, b3.y);
        }
    }

    float4 bv = make_float4(0.f, 0.f, 0.f, 0.f);
    if (bias) bv = *(const float4*)(bias + c0);
#pragma unroll
    for (int i = 0; i < 8; i++) {
        int gr = row0 + r0 + i;
        if (gr < M) {
            float x0, x1, x2, x3;
            unpack2(acc[i][0], x0, x1);
            unpack2(acc[i][1], x2, x3);
            x0 += bv.x; x1 += bv.y; x2 += bv.z; x3 += bv.w;
            if (RELU) {
                x0 = fmaxf(x0, 0.f); x1 = fmaxf(x1, 0.f);
                x2 = fmaxf(x2, 0.f); x3 = fmaxf(x3, 0.f);
            }
            *(float4*)(out + (size_t)gr * HH + c0) = make_float4(x0, x1, x2, x3);
        }
    }
}

template <bool HAS_AGG, bool RELU>
__global__ void __launch_bounds__(256, 2)
k_gemm128(const float* __restrict__ X, const float* __restrict__ AGG,
          const float* __restrict__ epsp, const float* __restrict__ W,
          const float* __restrict__ bias, float* __restrict__ out, int M) {
    extern __shared__ float sm[];
    gemm_body<HAS_AGG, RELU>(sm, X, AGG, epsp, W, bias, out, M, blockIdx.x * 64);
}

// batched mask GEMM: grid (GB, 2, K). y: top/bot half of mask_W1; z: expert.
__global__ void __launch_bounds__(256, 2)
k_gemm_mask(const float* __restrict__ Z, const float* __restrict__ mask_W1) {
    extern __shared__ float sm[];
    int k = blockIdx.z;
    const float* W = mask_W1 + ((size_t)k * 2 + blockIdx.y) * HH * HH;
    float* out = arena(k) + (1 + blockIdx.y) * (size_t)NN * HH;   // buf1 / buf2
    gemm_body<false, false>(sm, Z, nullptr, nullptr, W, nullptr, out, NN, blockIdx.x * 64);
}

// batched cls GEMM1: grid (GB, K): X=arena0, AGG=arena2, out=arena1
__global__ void __launch_bounds__(256, 2)
k_gemm_cls1(int l, const float* __restrict__ cls_eps, const float* __restrict__ cls_W1,
            const float* __restrict__ cls_b1) {
    extern __shared__ float sm[];
    int k = blockIdx.y;
    int wl = k * 3 + l;
    float* a = arena(k);
    gemm_body<true, true>(sm, a, a + 2 * (size_t)NN * HH, cls_eps + wl,
                          cls_W1 + (size_t)wl * HH * HH, cls_b1 + wl * HH,
                          a + (size_t)NN * HH, NN, blockIdx.x * 64);
}

// batched cls GEMM2: grid (GB, K): X=arena1, out=arena0
__global__ void __launch_bounds__(256, 2)
k_gemm_cls2(int l, const float* __restrict__ cls_W2, const float* __restrict__ cls_b2) {
    extern __shared__ float sm[];
    int k = blockIdx.y;
    int wl = k * 3 + l;
    float* a = arena(k);
    gemm_body<false, true>(sm, a + (size_t)NN * HH, nullptr, nullptr,
                           cls_W2 + (size_t)wl * HH * HH, cls_b2 + wl * HH,
                           a, NN, blockIdx.x * 64);
}

// ---------------- edge mask (warp per edge, batched over experts) ----------------
__global__ void k_edgemask(const int* __restrict__ src, const int* __restrict__ dst,
                           const float* __restrict__ u, const float* __restrict__ mask_b1,
                           const float* __restrict__ mask_w2, const float* __restrict__ mask_b2,
                           float* __restrict__ nm, float* __restrict__ em) {
    int e = blockIdx.x * (blockDim.x >> 5) + (threadIdx.x >> 5);
    if (e >= EE) return;
    int kk = blockIdx.y;
    float* a4 = arena(kk);
    const float* Abuf = a4 + (size_t)NN * HH;
    const float* Bbuf = a4 + 2 * (size_t)NN * HH;
    float* eon = a4 + 3 * (size_t)NN * HH;
    const float* b1 = mask_b1 + kk * HH;
    const float* w2 = mask_w2 + kk * HH;

    int lane = threadIdx.x & 31;
    int s = src[e], d = dst[e];
    float4 a = *(const float4*)(Abuf + (size_t)s * HH + (lane << 2));
    float4 b = *(const float4*)(Bbuf + (size_t)d * HH + (lane << 2));
    float4 bb = *(const float4*)(b1 + (lane << 2));
    float4 wv = *(const float4*)(w2 + (lane << 2));
    float h0 = fmaxf(a.x + b.x + bb.x, 0.f);
    float h1 = fmaxf(a.y + b.y + bb.y, 0.f);
    float h2 = fmaxf(a.z + b.z + bb.z, 0.f);
    float h3 = fmaxf(a.w + b.w + bb.w, 0.f);
    float p = h0 * wv.x + h1 * wv.y + h2 * wv.z + h3 * wv.w;
#pragma unroll
    for (int off = 16; off; off >>= 1) p += __shfl_xor_sync(0xffffffffu, p, off);
    if (lane == 0) {
        float eml = p + mask_b2[kk];
        float uu = u[(size_t)e * KK + kk];
        float g = -logf(-logf(uu + 1e-20f) + 1e-20f);
        float t = (eml + g) / 0.1f;
        float ys = 1.f / (1.f + expf(-t));
        float hard = (ys > 0.5f) ? 1.f : 0.f;
        float eo = (hard + ys) - ys;
        eon[e] = eo;
        em[(size_t)e * KK + kk] = eo;
        if (eo > 0.f) {
            nm[(size_t)s * KK + kk] = 1.f;
            nm[(size_t)d * KK + kk] = 1.f;
        }
    }
}

// ---------------- masked x (batched) ----------------
__global__ void k_maskx(const float* __restrict__ x, const float* __restrict__ nm) {
    int i = blockIdx.x * blockDim.x + threadIdx.x;
    if (i >= NN * 32) return;
    int kk = blockIdx.y;
    float* hout = arena(kk);
    int n = i >> 5;
    float m = nm[(size_t)n * KK + kk];
    float4 v = *(const float4*)(x + ((size_t)i << 2));
    v.x *= m; v.y *= m; v.z *= m; v.w *= m;
    *(float4*)(hout + ((size_t)i << 2)) = v;
}

// ---------------- h_orig mean pool ----------------
__global__ void k_pool(const float* __restrict__ h, float* __restrict__ out_base,
                       const int* __restrict__ cnt, const int* __restrict__ bstart) {
    int g = blockIdx.x;
    int c = blockIdx.y * 32 + threadIdx.x;
    int n0 = bstart[g], n = cnt[g];
    float a0 = 0.f, a1 = 0.f, a2 = 0.f, a3 = 0.f;
    int i = 0;
    for (; i + 4 <= n; i += 4) {
        a0 += h[(size_t)(n0 + i + 0) * HH + c];
        a1 += h[(size_t)(n0 + i + 1) * HH + c];
        a2 += h[(size_t)(n0 + i + 2) * HH + c];
        a3 += h[(size_t)(n0 + i + 3) * HH + c];
    }
    float acc = (a0 + a1) + (a2 + a3);
    for (; i < n; i++) acc += h[(size_t)(n0 + i) * HH + c];
    out_base[(size_t)g * HH + c] = acc / fmaxf((float)n, 1.f);
}

// ---------------- fused pool + head: grid (BB, K), 128 threads ----------------
__global__ void k_poolhead(const int* __restrict__ cnt, const int* __restrict__ bstart,
                           const float* __restrict__ head_W1, const float* __restrict__ head_b1,
                           const float* __restrict__ head_W2, const float* __restrict__ head_b2,
                           float* __restrict__ out_hstab, float* __restrict__ out_logits) {
    __shared__ float sh[128], T[128];
    int g = blockIdx.x, kk = blockIdx.y, c = threadIdx.x;
    const float* h = arena(kk);
    int n0 = bstart[g], n = cnt[g];
    float a0 = 0.f, a1 = 0.f, a2 = 0.f, a3 = 0.f;
    int i = 0;
    for (; i + 4 <= n; i += 4) {
        a0 += h[(size_t)(n0 + i + 0) * HH + c];
        a1 += h[(size_t)(n0 + i + 1) * HH + c];
        a2 += h[(size_t)(n0 + i + 2) * HH + c];
        a3 += h[(size_t)(n0 + i + 3) * HH + c];
    }
    float acc = (a0 + a1) + (a2 + a3);
    for (; i < n; i++) acc += h[(size_t)(n0 + i) * HH + c];
    float v = acc / fmaxf((float)n, 1.f);
    out_hstab[((size_t)g * KK + kk) * HH + c] = v;
    sh[c] = v;
    __syncthreads();

    const float* W1 = head_W1 + (size_t)kk * HH * HH;
    float t = head_b1[kk * HH + c];
#pragma unroll 8
    for (int j = 0; j < 128; j++) t += sh[j] * W1[j * HH + c];
    T[c] = fmaxf(t, 0.f);
    __syncthreads();
    if (c < 2) {
        const float* W2 = head_W2 + (size_t)kk * HH * 2;
        float s = head_b2[kk * 2 + c];
        for (int j = 0; j < 128; j++) s += T[j] * W2[j * 2 + c];
        out_logits[((size_t)g * KK + kk) * 2 + c] = s;
    }
}

// ---------------- launcher ----------------
extern "C" void kernel_launch(void* const* d_in, const int* in_sizes, int n_in,
                              void* d_out, int out_size) {
    const float* x       = (const float*)d_in[0];
    const int*   ei      = (const int*)d_in[1];
    const int*   src     = ei;
    const int*   dst     = ei + EE;
    const int*   batch   = (const int*)d_in[2];
    const float* u       = (const float*)d_in[3];
    const float* enc_W1  = (const float*)d_in[4];
    const float* enc_b1  = (const float*)d_in[5];
    const float* enc_W2  = (const float*)d_in[6];
    const float* enc_b2  = (const float*)d_in[7];
    const float* enc_eps = (const float*)d_in[8];
    const float* cls_W1  = (const float*)d_in[9];
    const float* cls_b1  = (const float*)d_in[10];
    const float* cls_W2  = (const float*)d_in[11];
    const float* cls_b2  = (const float*)d_in[12];
    const float* cls_eps = (const float*)d_in[13];
    const float* mask_W1 = (const float*)d_in[14];
    const float* mask_b1 = (const float*)d_in[15];
    const float* mask_W2 = (const float*)d_in[16];
    const float* mask_b2 = (const float*)d_in[17];
    const float* head_W1 = (const float*)d_in[18];
    const float* head_b1 = (const float*)d_in[19];
    const float* head_W2 = (const float*)d_in[20];
    const float* head_b2 = (const float*)d_in[21];
    float* out = (float*)d_out;

    unsigned char* base = nullptr;
    cudaGetSymbolAddress((void**)&base, g_scratch);
    float* p_Z      = (float*)(base + SC_Z);
    int*   p_deg    = (int*)(base + SC_DEG);
    int*   p_asrc   = (int*)(base + SC_ADJSRC);
    int*   p_aeid   = (int*)(base + SC_ADJEID);
    int*   p_cnt    = (int*)(base + SC_CNT);
    int*   p_bstart = (int*)(base + SC_BSTART);
    float* arena0   = (float*)(base + SC_EXP);   // expert 0 arena doubles as encoder temp

    cudaFuncSetAttribute(k_gemm128<true, true>,  cudaFuncAttributeMaxDynamicSharedMemorySize, SMEM_BYTES);
    cudaFuncSetAttribute(k_gemm128<false, true>, cudaFuncAttributeMaxDynamicSharedMemorySize, SMEM_BYTES);
    cudaFuncSetAttribute(k_gemm_mask,  cudaFuncAttributeMaxDynamicSharedMemorySize, SMEM_BYTES);
    cudaFuncSetAttribute(k_gemm_cls1,  cudaFuncAttributeMaxDynamicSharedMemorySize, SMEM_BYTES);
    cudaFuncSetAttribute(k_gemm_cls2,  cudaFuncAttributeMaxDynamicSharedMemorySize, SMEM_BYTES);

    const int GB = (NN + 63) / 64;
    const int AB = (NN + 7) / 8;
    const int EB = (EE + 7) / 8;

    // ---- setup ----
    k_zero_counts<<<(NN + 255) / 256, 256>>>(p_deg, p_cnt);
    k_build_adj<<<(EE + 255) / 256, 256>>>(src, dst, p_deg, p_asrc, p_aeid);
    k_sort_adj<<<(NN + 255) / 256, 256>>>(p_deg, p_asrc, p_aeid);
    k_count_batch<<<(NN + 255) / 256, 256>>>(batch, p_cnt);
    k_bstart<<<1, BB>>>(p_cnt, p_bstart);
    k_zero_nm<<<(NN * KK + 255) / 256, 256>>>(out + OFF_NM);

    // ---- encoder GIN stack (temps in expert-0 arena) ----
    float* t_h   = arena0;
    float* t_t   = arena0 + (size_t)NN * HH;
    float* t_agg = arena0 + 2 * (size_t)NN * HH;
    for (int l = 0; l < 3; l++) {
        const float* hin = (l == 0) ? x : t_h;
        k_aggregate_enc<<<AB, 256>>>(hin, t_agg, p_deg, p_asrc);
        k_gemm128<true, true><<<GB, 256, SMEM_BYTES>>>(
            hin, t_agg, enc_eps + l, enc_W1 + (size_t)l * HH * HH, enc_b1 + l * HH, t_t, NN);
        float* hout = (l == 2) ? p_Z : t_h;
        k_gemm128<false, true><<<GB, 256, SMEM_BYTES>>>(
            t_t, nullptr, nullptr, enc_W2 + (size_t)l * HH * HH, enc_b2 + l * HH, hout, NN);
    }

    // ---- h_orig ----
    k_pool<<<dim3(BB, 4), 32>>>(p_Z, out + OFF_HORIG, p_cnt, p_bstart);

    // ---- experts, batched stage-by-stage ----
    k_gemm_mask<<<dim3(GB, 2, KK), 256, SMEM_BYTES>>>(p_Z, mask_W1);
    k_edgemask<<<dim3(EB, KK), 256>>>(src, dst, u, mask_b1, mask_W2, mask_b2,
                                      out + OFF_NM, out + OFF_EM);
    k_maskx<<<dim3((NN * 32 + 255) / 256, KK), 256>>>(x, out + OFF_NM);
    for (int l = 0; l < 3; l++) {
        k_aggregate_cls<<<dim3(AB, KK), 256>>>(p_deg, p_asrc, p_aeid);
        k_gemm_cls1<<<dim3(GB, KK), 256, SMEM_BYTES>>>(l, cls_eps, cls_W1, cls_b1);
        k_gemm_cls2<<<dim3(GB, KK), 256, SMEM_BYTES>>>(l, cls_W2, cls_b2);
    }
    k_poolhead<<<dim3(BB, KK), 128>>>(p_cnt, p_bstart, head_W1, head_b1, head_W2, head_b2,
                                      out + OFF_HSTAB, out + OFF_LOGITS);
}